// round 12
// baseline (speedup 1.0000x reference)
#include <cuda_runtime.h>
#include <cstdint>

// GATv2 x3 layers. N=100000 nodes, E=1000000 edges, C=64, H=4, O=16.
//
// Per launch: build CSR by dst (hist -> scan -> scatter), then per layer:
//   1. gemm_lr  : xl = in@Wl, xr = in@Wr on TENSOR cores:
//                 mma.sync.m16n8k8 tf32 with 3xTF32 hi/lo split (~fp32 acc).
//   2. node_agg : one warp per dst node; two edges per iteration
//      (lane = 16*half + q, lane owns channels 4q..4q+3), depth-1 prefetch.
//      Fused logits+softmax+aggregate+bias; no atomics.
//      (segment-max skipped: alpha invariant to shift; logits are O(1))

#define NN 100000
#define EE 1000000
#define CC 64
#define HH 4
#define NBLK ((NN + 255) / 256)   // 391
#define FULL 0xffffffffu

// smem strides (floats) chosen for conflict-free MMA fragment loads
#define SW_STRIDE 136              // W rows: bank = (8t + g) % 32, all distinct
#define SX_STRIDE 68               // X rows: bank = (4g + t) % 32, all distinct
#define GEMM_SMEM_BYTES ((2 * 64 * SW_STRIDE + 2 * 64 * SX_STRIDE) * 4)  // 104448

// ---- scratch (device globals; no runtime allocation allowed) ----
__device__ float g_xl[NN * CC];
__device__ float g_xr[NN * CC];
__device__ float g_h[NN * CC];
__device__ int   g_srcs[EE];       // CSR: src sorted by dst
__device__ int   g_cnt[NN];
__device__ int   g_off[NN + 1];
__device__ int   g_cur[NN];
__device__ int   g_bsum[NBLK + 1];
__device__ int   g_bbase[NBLK + 1];
__device__ int   g_is64;

// leaky-relu(0.2): 0.6v + 0.4|v|
__device__ __forceinline__ float lrelu(float v) {
    return fmaf(0.4f, fabsf(v), 0.6f * v);
}

__device__ __forceinline__ uint32_t f2tf32(float f) {
    uint32_t u;
    asm("cvt.rna.tf32.f32 %0, %1;" : "=r"(u) : "f"(f));
    return u;
}

__device__ __forceinline__ void mma_tf32(float* d, const uint32_t* a,
                                         uint32_t b0, uint32_t b1) {
    asm volatile(
        "mma.sync.aligned.m16n8k8.row.col.f32.tf32.tf32.f32 "
        "{%0,%1,%2,%3}, {%4,%5,%6,%7}, {%8,%9}, {%0,%1,%2,%3};"
        : "+f"(d[0]), "+f"(d[1]), "+f"(d[2]), "+f"(d[3])
        : "r"(a[0]), "r"(a[1]), "r"(a[2]), "r"(a[3]), "r"(b0), "r"(b1));
}

// ---- detect int32 vs int64 edge_index (little-endian) ----
__global__ void detect_idx(const int* __restrict__ w) {
    int allz = 1;
#pragma unroll
    for (int i = 0; i < 128; i++) {
        if (w[2 * i + 1] != 0) { allz = 0; break; }
    }
    g_is64 = allz;
}

__global__ void zero_cnt() {
    int t = blockIdx.x * blockDim.x + threadIdx.x;
    if (t < NN) g_cnt[t] = 0;
}

// ---- dst histogram straight off edge_index ----
__global__ void hist_dst(const int* __restrict__ w) {
    int t = blockIdx.x * blockDim.x + threadIdx.x;
    if (t >= EE) return;
    int d = g_is64 ? w[2 * (EE + t)] : w[EE + t];
    d = min(max(d, 0), NN - 1);
    atomicAdd(&g_cnt[d], 1);
}

// ---- 3-kernel exclusive scan of g_cnt -> g_off / g_cur ----
__global__ void scan_part() {
    __shared__ int sh[256];
    int t = threadIdx.x;
    int i = blockIdx.x * 256 + t;
    int v = (i < NN) ? g_cnt[i] : 0;
    sh[t] = v;
    __syncthreads();
    for (int d = 128; d > 0; d >>= 1) {
        if (t < d) sh[t] += sh[t + d];
        __syncthreads();
    }
    if (t == 0) g_bsum[blockIdx.x] = sh[0];
}

__global__ void scan_top() {   // 1 block, 512 threads (NBLK=391)
    __shared__ int sh[512];
    int t = threadIdx.x;
    int v = (t < NBLK) ? g_bsum[t] : 0;
    sh[t] = v;
    __syncthreads();
    for (int d = 1; d < 512; d <<= 1) {
        int tmp = (t >= d) ? sh[t - d] : 0;
        __syncthreads();
        sh[t] += tmp;
        __syncthreads();
    }
    if (t < NBLK) g_bbase[t] = sh[t] - v;   // exclusive
}

__global__ void scan_apply() {
    __shared__ int sh[256];
    int t = threadIdx.x;
    int i = blockIdx.x * 256 + t;
    int v = (i < NN) ? g_cnt[i] : 0;
    sh[t] = v;
    __syncthreads();
    for (int d = 1; d < 256; d <<= 1) {
        int tmp = (t >= d) ? sh[t - d] : 0;
        __syncthreads();
        sh[t] += tmp;
        __syncthreads();
    }
    int excl = sh[t] - v + g_bbase[blockIdx.x];
    if (i < NN) {
        g_off[i] = excl;
        g_cur[i] = excl;
    }
    if (i == 0) g_off[NN] = EE;
}

__global__ void scatter_csr(const int* __restrict__ w) {
    int t = blockIdx.x * blockDim.x + threadIdx.x;
    if (t >= EE) return;
    int s, d;
    if (g_is64) {
        s = w[2 * t];
        d = w[2 * (EE + t)];
    } else {
        s = w[t];
        d = w[EE + t];
    }
    s = min(max(s, 0), NN - 1);
    d = min(max(d, 0), NN - 1);
    int pos = atomicAdd(&g_cur[d], 1);
    g_srcs[pos] = s;
}

// ---- xl = in @ Wl, xr = in @ Wr on tensor cores (3xTF32) ----
// Tile: 64 nodes x 128 cols per block, 8 warps.
// Warp w: m rows (w&3)*16..+15, n cols (w>>2)*64..+63 (8 m16n8 sub-tiles).
__global__ void __launch_bounds__(256) gemm_lr(
        const float* __restrict__ xin, int use_gh,
        const float* __restrict__ Wl, const float* __restrict__ Wr) {
    extern __shared__ float smf[];
    float* sWhi = smf;                           // [64][SW_STRIDE], cols 0..127
    float* sWlo = smf + 64 * SW_STRIDE;
    float* sxhi = smf + 2 * 64 * SW_STRIDE;      // [64][SX_STRIDE]
    float* sxlo = sxhi + 64 * SX_STRIDE;
    const float* in = use_gh ? g_h : xin;

    int tid = threadIdx.x;

    // W: hi/lo split into smem (cols 0..63 = Wl, 64..127 = Wr)
    for (int i = tid; i < 4096; i += 256) {
        int k = i >> 6, c = i & 63;
        float vl = Wl[i], vr = Wr[i];
        float hl = __uint_as_float(f2tf32(vl));
        float hr = __uint_as_float(f2tf32(vr));
        sWhi[k * SW_STRIDE + c]      = hl;
        sWhi[k * SW_STRIDE + 64 + c] = hr;
        sWlo[k * SW_STRIDE + c]      = __uint_as_float(f2tf32(vl - hl));
        sWlo[k * SW_STRIDE + 64 + c] = __uint_as_float(f2tf32(vr - hr));
    }
    // X tile: hi/lo split
    int base = blockIdx.x * 64;
    for (int i = tid; i < 4096; i += 256) {
        int n = i >> 6, k = i & 63;
        int node = base + n;
        float v = (node < NN) ? in[(size_t)node * 64 + k] : 0.f;
        float h = __uint_as_float(f2tf32(v));
        sxhi[n * SX_STRIDE + k] = h;
        sxlo[n * SX_STRIDE + k] = __uint_as_float(f2tf32(v - h));
    }
    __syncthreads();

    int w = tid >> 5, lane = tid & 31;
    int g = lane >> 2, t = lane & 3;
    int m0 = (w & 3) << 4;
    int nb = (w >> 2) << 6;

    float acc[8][4];
#pragma unroll
    for (int s = 0; s < 8; s++) {
        acc[s][0] = 0.f; acc[s][1] = 0.f; acc[s][2] = 0.f; acc[s][3] = 0.f;
    }

#pragma unroll
    for (int ks = 0; ks < 8; ks++) {
        int k0 = ks * 8;
        int ra = (m0 + g) * SX_STRIDE + k0 + t;
        int rb = (m0 + g + 8) * SX_STRIDE + k0 + t;
        uint32_t ah[4], al[4];
        ah[0] = __float_as_uint(sxhi[ra]);
        ah[1] = __float_as_uint(sxhi[rb]);
        ah[2] = __float_as_uint(sxhi[ra + 4]);
        ah[3] = __float_as_uint(sxhi[rb + 4]);
        al[0] = __float_as_uint(sxlo[ra]);
        al[1] = __float_as_uint(sxlo[rb]);
        al[2] = __float_as_uint(sxlo[ra + 4]);
        al[3] = __float_as_uint(sxlo[rb + 4]);
#pragma unroll
        for (int s = 0; s < 8; s++) {
            int col = nb + s * 8 + g;
            int rb0 = (k0 + t) * SW_STRIDE + col;
            int rb1 = (k0 + t + 4) * SW_STRIDE + col;
            uint32_t bh0 = __float_as_uint(sWhi[rb0]);
            uint32_t bh1 = __float_as_uint(sWhi[rb1]);
            uint32_t bl0 = __float_as_uint(sWlo[rb0]);
            uint32_t bl1 = __float_as_uint(sWlo[rb1]);
            mma_tf32(acc[s], ah, bh0, bh1);   // hi*hi
            mma_tf32(acc[s], ah, bl0, bl1);   // hi*lo
            mma_tf32(acc[s], al, bh0, bh1);   // lo*hi
        }
    }

    // D element (m0+g(+8), nb + s*8 + 2t(+1))
    int node0 = base + m0 + g;
    int node1 = node0 + 8;
#pragma unroll
    for (int s = 0; s < 8; s++) {
        int col = nb + s * 8 + 2 * t;
        float* dst0;
        float* dst1;
        if (col < 64) {
            dst0 = g_xl + (size_t)node0 * 64 + col;
            dst1 = g_xl + (size_t)node1 * 64 + col;
        } else {
            dst0 = g_xr + (size_t)node0 * 64 + col - 64;
            dst1 = g_xr + (size_t)node1 * 64 + col - 64;
        }
        if (node0 < NN) *(float2*)dst0 = make_float2(acc[s][0], acc[s][1]);
        if (node1 < NN) *(float2*)dst1 = make_float2(acc[s][2], acc[s][3]);
    }
}

// ---- fused edge phase: one warp per dst node, 2 edges per iteration ----
__global__ void node_agg(const float* __restrict__ a, const float* __restrict__ b,
                         float* __restrict__ dout, int layer) {
    int gw = (blockIdx.x * blockDim.x + threadIdx.x) >> 5;
    int lane = threadIdx.x & 31;
    if (gw >= NN) return;
    int d = gw;
    int half = lane >> 4;
    int q = lane & 15;
    int c0 = q * 4;

    float4 xr4 = *(const float4*)(g_xr + (size_t)d * 64 + c0);
    float4 a4  = *(const float4*)(a + c0);

    int beg = g_off[d], end = g_off[d + 1];
    float denom = 0.f;
    float ac0 = 0.f, ac1 = 0.f, ac2 = 0.f, ac3 = 0.f;

    for (int base = beg; base < end; base += 32) {
        int n = min(32, end - base);
        int my_s = (base + lane < end) ? g_srcs[base + lane] : 0;
        int npair = (n + 1) >> 1;

        int s = __shfl_sync(FULL, my_s, half);     // edge {0,1}
        float4 xl = *(const float4*)(g_xl + (size_t)s * 64 + c0);

        for (int jp = 0; jp < npair; jp++) {
            float4 cur = xl;
            int ecur = 2 * jp + half;
            if (jp + 1 < npair) {
                int sn = __shfl_sync(FULL, my_s, 2 * (jp + 1) + half);
                xl = *(const float4*)(g_xl + (size_t)sn * 64 + c0);
            }
            float p = lrelu(cur.x + xr4.x) * a4.x
                    + lrelu(cur.y + xr4.y) * a4.y
                    + lrelu(cur.z + xr4.z) * a4.z
                    + lrelu(cur.w + xr4.w) * a4.w;
            p += __shfl_xor_sync(FULL, p, 1);
            p += __shfl_xor_sync(FULL, p, 2);
            float ex = __expf(p);
            if (ecur >= n) ex = 0.f;               // odd tail: upper half idle
            denom += ex;
            ac0 += ex * cur.x;
            ac1 += ex * cur.y;
            ac2 += ex * cur.z;
            ac3 += ex * cur.w;
        }
    }

    denom += __shfl_xor_sync(FULL, denom, 16);
    ac0   += __shfl_xor_sync(FULL, ac0, 16);
    ac1   += __shfl_xor_sync(FULL, ac1, 16);
    ac2   += __shfl_xor_sync(FULL, ac2, 16);
    ac3   += __shfl_xor_sync(FULL, ac3, 16);

    if (half == 0) {
        float inv = 1.f / (denom + 1e-16f);
        float4 b4 = *(const float4*)(b + c0);
        float4 v = make_float4(ac0 * inv + b4.x, ac1 * inv + b4.y,
                               ac2 * inv + b4.z, ac3 * inv + b4.w);
        if (layer < 2) {
            v.x = fmaxf(v.x, 0.f); v.y = fmaxf(v.y, 0.f);
            v.z = fmaxf(v.z, 0.f); v.w = fmaxf(v.w, 0.f);
            *(float4*)(g_h + (size_t)d * 64 + c0) = v;
        } else {
            *(float4*)(dout + (size_t)d * 64 + c0) = v;
        }
    }
}

extern "C" void kernel_launch(void* const* d_in, const int* in_sizes, int n_in,
                              void* d_out, int out_size) {
    const float* x = (const float*)d_in[0];
    const int* ei = (const int*)d_in[1];

    cudaFuncSetAttribute(gemm_lr, cudaFuncAttributeMaxDynamicSharedMemorySize,
                         GEMM_SMEM_BYTES);

    detect_idx<<<1, 1>>>(ei);
    zero_cnt<<<NBLK, 256>>>();
    hist_dst<<<(EE + 255) / 256, 256>>>(ei);
    // layer-0 GEMM is CSR-independent; launch index 3 = profiler sample slot
    gemm_lr<<<(NN + 63) / 64, 256, GEMM_SMEM_BYTES>>>(
        x, 0, (const float*)d_in[2], (const float*)d_in[3]);
    scan_part<<<NBLK, 256>>>();
    scan_top<<<1, 512>>>();
    scan_apply<<<NBLK, 256>>>();
    scatter_csr<<<(EE + 255) / 256, 256>>>(ei);

    for (int l = 0; l < 3; l++) {
        const float* a = (const float*)d_in[4 + 4 * l];
        const float* b = (const float*)d_in[5 + 4 * l];
        if (l > 0) {
            gemm_lr<<<(NN + 63) / 64, 256, GEMM_SMEM_BYTES>>>(
                x, 1, (const float*)d_in[2 + 4 * l],
                (const float*)d_in[3 + 4 * l]);
        }
        node_agg<<<(NN * 32 + 255) / 256, 256>>>(a, b, (float*)d_out, l);
    }
}

// round 13
// speedup vs baseline: 1.4003x; 1.4003x over previous
#include <cuda_runtime.h>
#include <cstdint>

// GATv2 x3 layers. N=100000 nodes, E=1000000 edges, C=64, H=4, O=16.
//
// Per launch: build CSR by dst (hist -> scan -> scatter), then per layer:
//   1. gemm_lr  : xl = in@Wl, xr = in@Wr on TENSOR cores.
//      3xTF32 (hh + hl + lh) with register-side Dekker split:
//      hi = bits & 0xFFFFE000, lo = v - hi  (MMA truncates mantissas anyway,
//      so no cvt needed). W and X stored ONCE in smem (52 KB) -> 3-4 blk/SM.
//   2. node_agg : one warp per dst node; two edges per iteration
//      (lane = 16*half + q, lane owns channels 4q..4q+3), depth-1 prefetch.
//      Fused logits+softmax+aggregate+bias; no atomics.
//      (segment-max skipped: alpha invariant to shift; logits are O(1))

#define NN 100000
#define EE 1000000
#define CC 64
#define HH 4
#define NBLK ((NN + 255) / 256)   // 391
#define FULL 0xffffffffu

// smem strides (floats) chosen for conflict-free MMA fragment loads
#define SW_STRIDE 136              // W rows: bank = (8t + g) % 32, all distinct
#define SX_STRIDE 68               // X rows: bank = (4g + t) % 32, all distinct
#define GEMM_SMEM_BYTES ((64 * SW_STRIDE + 64 * SX_STRIDE) * 4)   // 52224

// ---- scratch (device globals; no runtime allocation allowed) ----
__device__ float g_xl[NN * CC];
__device__ float g_xr[NN * CC];
__device__ float g_h[NN * CC];
__device__ int   g_srcs[EE];       // CSR: src sorted by dst
__device__ int   g_cnt[NN];
__device__ int   g_off[NN + 1];
__device__ int   g_cur[NN];
__device__ int   g_bsum[NBLK + 1];
__device__ int   g_bbase[NBLK + 1];
__device__ int   g_is64;

// leaky-relu(0.2): 0.6v + 0.4|v|
__device__ __forceinline__ float lrelu(float v) {
    return fmaf(0.4f, fabsf(v), 0.6f * v);
}

// Dekker-style tf32 split: hi = top mantissa bits (exact fp32), lo = v - hi.
// The MMA unit truncates operand mantissas to tf32, so lo needs no rounding.
__device__ __forceinline__ void tf32_split(float v, uint32_t& hi, uint32_t& lo) {
    uint32_t h = __float_as_uint(v) & 0xFFFFE000u;
    hi = h;
    lo = __float_as_uint(v - __uint_as_float(h));
}

__device__ __forceinline__ void mma_tf32(float* d, const uint32_t* a,
                                         uint32_t b0, uint32_t b1) {
    asm volatile(
        "mma.sync.aligned.m16n8k8.row.col.f32.tf32.tf32.f32 "
        "{%0,%1,%2,%3}, {%4,%5,%6,%7}, {%8,%9}, {%0,%1,%2,%3};"
        : "+f"(d[0]), "+f"(d[1]), "+f"(d[2]), "+f"(d[3])
        : "r"(a[0]), "r"(a[1]), "r"(a[2]), "r"(a[3]), "r"(b0), "r"(b1));
}

// ---- detect int32 vs int64 edge_index (little-endian) ----
__global__ void detect_idx(const int* __restrict__ w) {
    int allz = 1;
#pragma unroll
    for (int i = 0; i < 128; i++) {
        if (w[2 * i + 1] != 0) { allz = 0; break; }
    }
    g_is64 = allz;
}

__global__ void zero_cnt() {
    int t = blockIdx.x * blockDim.x + threadIdx.x;
    if (t < NN) g_cnt[t] = 0;
}

// ---- dst histogram straight off edge_index ----
__global__ void hist_dst(const int* __restrict__ w) {
    int t = blockIdx.x * blockDim.x + threadIdx.x;
    if (t >= EE) return;
    int d = g_is64 ? w[2 * (EE + t)] : w[EE + t];
    d = min(max(d, 0), NN - 1);
    atomicAdd(&g_cnt[d], 1);
}

// ---- 3-kernel exclusive scan of g_cnt -> g_off / g_cur ----
__global__ void scan_part() {
    __shared__ int sh[256];
    int t = threadIdx.x;
    int i = blockIdx.x * 256 + t;
    int v = (i < NN) ? g_cnt[i] : 0;
    sh[t] = v;
    __syncthreads();
    for (int d = 128; d > 0; d >>= 1) {
        if (t < d) sh[t] += sh[t + d];
        __syncthreads();
    }
    if (t == 0) g_bsum[blockIdx.x] = sh[0];
}

__global__ void scan_top() {   // 1 block, 512 threads (NBLK=391)
    __shared__ int sh[512];
    int t = threadIdx.x;
    int v = (t < NBLK) ? g_bsum[t] : 0;
    sh[t] = v;
    __syncthreads();
    for (int d = 1; d < 512; d <<= 1) {
        int tmp = (t >= d) ? sh[t - d] : 0;
        __syncthreads();
        sh[t] += tmp;
        __syncthreads();
    }
    if (t < NBLK) g_bbase[t] = sh[t] - v;   // exclusive
}

__global__ void scan_apply() {
    __shared__ int sh[256];
    int t = threadIdx.x;
    int i = blockIdx.x * 256 + t;
    int v = (i < NN) ? g_cnt[i] : 0;
    sh[t] = v;
    __syncthreads();
    for (int d = 1; d < 256; d <<= 1) {
        int tmp = (t >= d) ? sh[t - d] : 0;
        __syncthreads();
        sh[t] += tmp;
        __syncthreads();
    }
    int excl = sh[t] - v + g_bbase[blockIdx.x];
    if (i < NN) {
        g_off[i] = excl;
        g_cur[i] = excl;
    }
    if (i == 0) g_off[NN] = EE;
}

__global__ void scatter_csr(const int* __restrict__ w) {
    int t = blockIdx.x * blockDim.x + threadIdx.x;
    if (t >= EE) return;
    int s, d;
    if (g_is64) {
        s = w[2 * t];
        d = w[2 * (EE + t)];
    } else {
        s = w[t];
        d = w[EE + t];
    }
    s = min(max(s, 0), NN - 1);
    d = min(max(d, 0), NN - 1);
    int pos = atomicAdd(&g_cur[d], 1);
    g_srcs[pos] = s;
}

// ---- xl = in @ Wl, xr = in @ Wr on tensor cores (3xTF32) ----
// Tile: 64 nodes x 128 cols per block, 8 warps.
// Warp w: m rows (w&3)*16..+15, n cols (w>>2)*64..+63 (8 m16n8 sub-tiles).
// W and X live in smem ONCE (fp32); hi/lo split happens in registers.
__global__ void __launch_bounds__(256) gemm_lr(
        const float* __restrict__ xin, int use_gh,
        const float* __restrict__ Wl, const float* __restrict__ Wr) {
    extern __shared__ float smf[];
    float* sW = smf;                       // [64][SW_STRIDE], cols 0..127
    float* sx = smf + 64 * SW_STRIDE;      // [64][SX_STRIDE]
    const float* in = use_gh ? g_h : xin;

    int tid = threadIdx.x;

    for (int i = tid; i < 4096; i += 256) {
        int k = i >> 6, c = i & 63;
        sW[k * SW_STRIDE + c]      = Wl[i];
        sW[k * SW_STRIDE + 64 + c] = Wr[i];
    }
    int base = blockIdx.x * 64;
    for (int i = tid; i < 1024; i += 256) {        // 64 nodes x 16 float4
        int n = i >> 4, q = i & 15;
        int node = base + n;
        float4 v = make_float4(0.f, 0.f, 0.f, 0.f);
        if (node < NN) v = ((const float4*)(in + (size_t)node * 64))[q];
        sx[n * SX_STRIDE + 4 * q]     = v.x;
        sx[n * SX_STRIDE + 4 * q + 1] = v.y;
        sx[n * SX_STRIDE + 4 * q + 2] = v.z;
        sx[n * SX_STRIDE + 4 * q + 3] = v.w;
    }
    __syncthreads();

    int w = tid >> 5, lane = tid & 31;
    int g = lane >> 2, t = lane & 3;
    int m0 = (w & 3) << 4;
    int nb = (w >> 2) << 6;

    float acc[8][4];
#pragma unroll
    for (int s = 0; s < 8; s++) {
        acc[s][0] = 0.f; acc[s][1] = 0.f; acc[s][2] = 0.f; acc[s][3] = 0.f;
    }

#pragma unroll
    for (int ks = 0; ks < 8; ks++) {
        int k0 = ks * 8;
        int ra = (m0 + g) * SX_STRIDE + k0 + t;
        int rb = (m0 + g + 8) * SX_STRIDE + k0 + t;
        uint32_t ah[4], al[4];
        tf32_split(sx[ra],     ah[0], al[0]);
        tf32_split(sx[rb],     ah[1], al[1]);
        tf32_split(sx[ra + 4], ah[2], al[2]);
        tf32_split(sx[rb + 4], ah[3], al[3]);
#pragma unroll
        for (int s = 0; s < 8; s++) {
            int col = nb + s * 8 + g;
            uint32_t bh0, bl0, bh1, bl1;
            tf32_split(sW[(k0 + t) * SW_STRIDE + col],     bh0, bl0);
            tf32_split(sW[(k0 + t + 4) * SW_STRIDE + col], bh1, bl1);
            mma_tf32(acc[s], ah, bh0, bh1);   // hi*hi
            mma_tf32(acc[s], ah, bl0, bl1);   // hi*lo
            mma_tf32(acc[s], al, bh0, bh1);   // lo*hi
        }
    }

    // D element (m0+g(+8), nb + s*8 + 2t(+1))
    int node0 = base + m0 + g;
    int node1 = node0 + 8;
#pragma unroll
    for (int s = 0; s < 8; s++) {
        int col = nb + s * 8 + 2 * t;
        float* dst0;
        float* dst1;
        if (col < 64) {
            dst0 = g_xl + (size_t)node0 * 64 + col;
            dst1 = g_xl + (size_t)node1 * 64 + col;
        } else {
            dst0 = g_xr + (size_t)node0 * 64 + col - 64;
            dst1 = g_xr + (size_t)node1 * 64 + col - 64;
        }
        if (node0 < NN) *(float2*)dst0 = make_float2(acc[s][0], acc[s][1]);
        if (node1 < NN) *(float2*)dst1 = make_float2(acc[s][2], acc[s][3]);
    }
}

// ---- fused edge phase: one warp per dst node, 2 edges per iteration ----
__global__ void node_agg(const float* __restrict__ a, const float* __restrict__ b,
                         float* __restrict__ dout, int layer) {
    int gw = (blockIdx.x * blockDim.x + threadIdx.x) >> 5;
    int lane = threadIdx.x & 31;
    if (gw >= NN) return;
    int d = gw;
    int half = lane >> 4;
    int q = lane & 15;
    int c0 = q * 4;

    float4 xr4 = *(const float4*)(g_xr + (size_t)d * 64 + c0);
    float4 a4  = *(const float4*)(a + c0);

    int beg = g_off[d], end = g_off[d + 1];
    float denom = 0.f;
    float ac0 = 0.f, ac1 = 0.f, ac2 = 0.f, ac3 = 0.f;

    for (int base = beg; base < end; base += 32) {
        int n = min(32, end - base);
        int my_s = (base + lane < end) ? g_srcs[base + lane] : 0;
        int npair = (n + 1) >> 1;

        int s = __shfl_sync(FULL, my_s, half);     // edge {0,1}
        float4 xl = *(const float4*)(g_xl + (size_t)s * 64 + c0);

        for (int jp = 0; jp < npair; jp++) {
            float4 cur = xl;
            int ecur = 2 * jp + half;
            if (jp + 1 < npair) {
                int sn = __shfl_sync(FULL, my_s, 2 * (jp + 1) + half);
                xl = *(const float4*)(g_xl + (size_t)sn * 64 + c0);
            }
            float p = lrelu(cur.x + xr4.x) * a4.x
                    + lrelu(cur.y + xr4.y) * a4.y
                    + lrelu(cur.z + xr4.z) * a4.z
                    + lrelu(cur.w + xr4.w) * a4.w;
            p += __shfl_xor_sync(FULL, p, 1);
            p += __shfl_xor_sync(FULL, p, 2);
            float ex = __expf(p);
            if (ecur >= n) ex = 0.f;               // odd tail: upper half idle
            denom += ex;
            ac0 += ex * cur.x;
            ac1 += ex * cur.y;
            ac2 += ex * cur.z;
            ac3 += ex * cur.w;
        }
    }

    denom += __shfl_xor_sync(FULL, denom, 16);
    ac0   += __shfl_xor_sync(FULL, ac0, 16);
    ac1   += __shfl_xor_sync(FULL, ac1, 16);
    ac2   += __shfl_xor_sync(FULL, ac2, 16);
    ac3   += __shfl_xor_sync(FULL, ac3, 16);

    if (half == 0) {
        float inv = 1.f / (denom + 1e-16f);
        float4 b4 = *(const float4*)(b + c0);
        float4 v = make_float4(ac0 * inv + b4.x, ac1 * inv + b4.y,
                               ac2 * inv + b4.z, ac3 * inv + b4.w);
        if (layer < 2) {
            v.x = fmaxf(v.x, 0.f); v.y = fmaxf(v.y, 0.f);
            v.z = fmaxf(v.z, 0.f); v.w = fmaxf(v.w, 0.f);
            *(float4*)(g_h + (size_t)d * 64 + c0) = v;
        } else {
            *(float4*)(dout + (size_t)d * 64 + c0) = v;
        }
    }
}

extern "C" void kernel_launch(void* const* d_in, const int* in_sizes, int n_in,
                              void* d_out, int out_size) {
    const float* x = (const float*)d_in[0];
    const int* ei = (const int*)d_in[1];

    cudaFuncSetAttribute(gemm_lr, cudaFuncAttributeMaxDynamicSharedMemorySize,
                         GEMM_SMEM_BYTES);

    detect_idx<<<1, 1>>>(ei);
    zero_cnt<<<NBLK, 256>>>();
    hist_dst<<<(EE + 255) / 256, 256>>>(ei);
    // layer-0 GEMM is CSR-independent; launch index 3 = profiler sample slot
    gemm_lr<<<(NN + 63) / 64, 256, GEMM_SMEM_BYTES>>>(
        x, 0, (const float*)d_in[2], (const float*)d_in[3]);
    scan_part<<<NBLK, 256>>>();
    scan_top<<<1, 512>>>();
    scan_apply<<<NBLK, 256>>>();
    scatter_csr<<<(EE + 255) / 256, 256>>>(ei);

    for (int l = 0; l < 3; l++) {
        const float* a = (const float*)d_in[4 + 4 * l];
        const float* b = (const float*)d_in[5 + 4 * l];
        if (l > 0) {
            gemm_lr<<<(NN + 63) / 64, 256, GEMM_SMEM_BYTES>>>(
                x, 1, (const float*)d_in[2 + 4 * l],
                (const float*)d_in[3 + 4 * l]);
        }
        node_agg<<<(NN * 32 + 255) / 256, 256>>>(a, b, (float*)d_out, l);
    }
}

// round 14
// speedup vs baseline: 1.4244x; 1.0172x over previous
#include <cuda_runtime.h>
#include <cstdint>

// GATv2 x3 layers. N=100000 nodes, E=1000000 edges, C=64, H=4, O=16.
//
// Round-14 change: CSR build (hist -> scans -> scatter) runs on a SECOND
// stream, overlapped with the (independent) layer-0 tensor-core GEMM.
// Fork/join via events — the capture-safe pattern, producing a graph with
// two parallel branches. Compute kernels identical to the 322 us champion.

#define NN 100000
#define EE 1000000
#define CC 64
#define HH 4
#define NBLK ((NN + 255) / 256)   // 391
#define FULL 0xffffffffu

// smem strides (floats) chosen for conflict-free MMA fragment loads
#define SW_STRIDE 136              // W rows: bank = (8t + g) % 32, all distinct
#define SX_STRIDE 68               // X rows: bank = (4g + t) % 32, all distinct
#define GEMM_SMEM_BYTES ((64 * SW_STRIDE + 64 * SX_STRIDE) * 4)   // 52224

// ---- scratch (device globals; no runtime allocation allowed) ----
__device__ float g_xl[NN * CC];
__device__ float g_xr[NN * CC];
__device__ float g_h[NN * CC];
__device__ int   g_srcs[EE];       // CSR: src sorted by dst
__device__ int   g_cnt[NN];
__device__ int   g_off[NN + 1];
__device__ int   g_cur[NN];
__device__ int   g_bsum[NBLK + 1];
__device__ int   g_bbase[NBLK + 1];
__device__ int   g_is64;

// leaky-relu(0.2): 0.6v + 0.4|v|
__device__ __forceinline__ float lrelu(float v) {
    return fmaf(0.4f, fabsf(v), 0.6f * v);
}

// Dekker-style tf32 split: hi = top mantissa bits (exact fp32), lo = v - hi.
__device__ __forceinline__ void tf32_split(float v, uint32_t& hi, uint32_t& lo) {
    uint32_t h = __float_as_uint(v) & 0xFFFFE000u;
    hi = h;
    lo = __float_as_uint(v - __uint_as_float(h));
}

__device__ __forceinline__ void mma_tf32(float* d, const uint32_t* a,
                                         uint32_t b0, uint32_t b1) {
    asm volatile(
        "mma.sync.aligned.m16n8k8.row.col.f32.tf32.tf32.f32 "
        "{%0,%1,%2,%3}, {%4,%5,%6,%7}, {%8,%9}, {%0,%1,%2,%3};"
        : "+f"(d[0]), "+f"(d[1]), "+f"(d[2]), "+f"(d[3])
        : "r"(a[0]), "r"(a[1]), "r"(a[2]), "r"(a[3]), "r"(b0), "r"(b1));
}

// ---- detect int32 vs int64 edge_index + zero counts (one kernel) ----
__global__ void init_csr(const int* __restrict__ w) {
    int t = blockIdx.x * blockDim.x + threadIdx.x;
    if (t < NN) g_cnt[t] = 0;
    if (t == 0) {
        int allz = 1;
#pragma unroll
        for (int i = 0; i < 128; i++) {
            if (w[2 * i + 1] != 0) { allz = 0; break; }
        }
        g_is64 = allz;
    }
}

// ---- dst histogram straight off edge_index ----
__global__ void hist_dst(const int* __restrict__ w) {
    int t = blockIdx.x * blockDim.x + threadIdx.x;
    if (t >= EE) return;
    int d = g_is64 ? w[2 * (EE + t)] : w[EE + t];
    d = min(max(d, 0), NN - 1);
    atomicAdd(&g_cnt[d], 1);
}

// ---- 3-kernel exclusive scan of g_cnt -> g_off / g_cur ----
__global__ void scan_part() {
    __shared__ int sh[256];
    int t = threadIdx.x;
    int i = blockIdx.x * 256 + t;
    int v = (i < NN) ? g_cnt[i] : 0;
    sh[t] = v;
    __syncthreads();
    for (int d = 128; d > 0; d >>= 1) {
        if (t < d) sh[t] += sh[t + d];
        __syncthreads();
    }
    if (t == 0) g_bsum[blockIdx.x] = sh[0];
}

__global__ void scan_top() {   // 1 block, 512 threads (NBLK=391)
    __shared__ int sh[512];
    int t = threadIdx.x;
    int v = (t < NBLK) ? g_bsum[t] : 0;
    sh[t] = v;
    __syncthreads();
    for (int d = 1; d < 512; d <<= 1) {
        int tmp = (t >= d) ? sh[t - d] : 0;
        __syncthreads();
        sh[t] += tmp;
        __syncthreads();
    }
    if (t < NBLK) g_bbase[t] = sh[t] - v;   // exclusive
}

__global__ void scan_apply() {
    __shared__ int sh[256];
    int t = threadIdx.x;
    int i = blockIdx.x * 256 + t;
    int v = (i < NN) ? g_cnt[i] : 0;
    sh[t] = v;
    __syncthreads();
    for (int d = 1; d < 256; d <<= 1) {
        int tmp = (t >= d) ? sh[t - d] : 0;
        __syncthreads();
        sh[t] += tmp;
        __syncthreads();
    }
    int excl = sh[t] - v + g_bbase[blockIdx.x];
    if (i < NN) {
        g_off[i] = excl;
        g_cur[i] = excl;
    }
    if (i == 0) g_off[NN] = EE;
}

__global__ void scatter_csr(const int* __restrict__ w) {
    int t = blockIdx.x * blockDim.x + threadIdx.x;
    if (t >= EE) return;
    int s, d;
    if (g_is64) {
        s = w[2 * t];
        d = w[2 * (EE + t)];
    } else {
        s = w[t];
        d = w[EE + t];
    }
    s = min(max(s, 0), NN - 1);
    d = min(max(d, 0), NN - 1);
    int pos = atomicAdd(&g_cur[d], 1);
    g_srcs[pos] = s;
}

// ---- xl = in @ Wl, xr = in @ Wr on tensor cores (3xTF32) ----
__global__ void __launch_bounds__(256) gemm_lr(
        const float* __restrict__ xin, int use_gh,
        const float* __restrict__ Wl, const float* __restrict__ Wr) {
    extern __shared__ float smf[];
    float* sW = smf;                       // [64][SW_STRIDE], cols 0..127
    float* sx = smf + 64 * SW_STRIDE;      // [64][SX_STRIDE]
    const float* in = use_gh ? g_h : xin;

    int tid = threadIdx.x;

    for (int i = tid; i < 4096; i += 256) {
        int k = i >> 6, c = i & 63;
        sW[k * SW_STRIDE + c]      = Wl[i];
        sW[k * SW_STRIDE + 64 + c] = Wr[i];
    }
    int base = blockIdx.x * 64;
    for (int i = tid; i < 1024; i += 256) {        // 64 nodes x 16 float4
        int n = i >> 4, q = i & 15;
        int node = base + n;
        float4 v = make_float4(0.f, 0.f, 0.f, 0.f);
        if (node < NN) v = ((const float4*)(in + (size_t)node * 64))[q];
        sx[n * SX_STRIDE + 4 * q]     = v.x;
        sx[n * SX_STRIDE + 4 * q + 1] = v.y;
        sx[n * SX_STRIDE + 4 * q + 2] = v.z;
        sx[n * SX_STRIDE + 4 * q + 3] = v.w;
    }
    __syncthreads();

    int w = tid >> 5, lane = tid & 31;
    int g = lane >> 2, t = lane & 3;
    int m0 = (w & 3) << 4;
    int nb = (w >> 2) << 6;

    float acc[8][4];
#pragma unroll
    for (int s = 0; s < 8; s++) {
        acc[s][0] = 0.f; acc[s][1] = 0.f; acc[s][2] = 0.f; acc[s][3] = 0.f;
    }

#pragma unroll
    for (int ks = 0; ks < 8; ks++) {
        int k0 = ks * 8;
        int ra = (m0 + g) * SX_STRIDE + k0 + t;
        int rb = (m0 + g + 8) * SX_STRIDE + k0 + t;
        uint32_t ah[4], al[4];
        tf32_split(sx[ra],     ah[0], al[0]);
        tf32_split(sx[rb],     ah[1], al[1]);
        tf32_split(sx[ra + 4], ah[2], al[2]);
        tf32_split(sx[rb + 4], ah[3], al[3]);
#pragma unroll
        for (int s = 0; s < 8; s++) {
            int col = nb + s * 8 + g;
            uint32_t bh0, bl0, bh1, bl1;
            tf32_split(sW[(k0 + t) * SW_STRIDE + col],     bh0, bl0);
            tf32_split(sW[(k0 + t + 4) * SW_STRIDE + col], bh1, bl1);
            mma_tf32(acc[s], ah, bh0, bh1);   // hi*hi
            mma_tf32(acc[s], ah, bl0, bl1);   // hi*lo
            mma_tf32(acc[s], al, bh0, bh1);   // lo*hi
        }
    }

    int node0 = base + m0 + g;
    int node1 = node0 + 8;
#pragma unroll
    for (int s = 0; s < 8; s++) {
        int col = nb + s * 8 + 2 * t;
        float* dst0;
        float* dst1;
        if (col < 64) {
            dst0 = g_xl + (size_t)node0 * 64 + col;
            dst1 = g_xl + (size_t)node1 * 64 + col;
        } else {
            dst0 = g_xr + (size_t)node0 * 64 + col - 64;
            dst1 = g_xr + (size_t)node1 * 64 + col - 64;
        }
        if (node0 < NN) *(float2*)dst0 = make_float2(acc[s][0], acc[s][1]);
        if (node1 < NN) *(float2*)dst1 = make_float2(acc[s][2], acc[s][3]);
    }
}

// ---- fused edge phase: one warp per dst node, 2 edges per iteration ----
__global__ void node_agg(const float* __restrict__ a, const float* __restrict__ b,
                         float* __restrict__ dout, int layer) {
    int gw = (blockIdx.x * blockDim.x + threadIdx.x) >> 5;
    int lane = threadIdx.x & 31;
    if (gw >= NN) return;
    int d = gw;
    int half = lane >> 4;
    int q = lane & 15;
    int c0 = q * 4;

    float4 xr4 = *(const float4*)(g_xr + (size_t)d * 64 + c0);
    float4 a4  = *(const float4*)(a + c0);

    int beg = g_off[d], end = g_off[d + 1];
    float denom = 0.f;
    float ac0 = 0.f, ac1 = 0.f, ac2 = 0.f, ac3 = 0.f;

    for (int base = beg; base < end; base += 32) {
        int n = min(32, end - base);
        int my_s = (base + lane < end) ? g_srcs[base + lane] : 0;
        int npair = (n + 1) >> 1;

        int s = __shfl_sync(FULL, my_s, half);     // edge {0,1}
        float4 xl = *(const float4*)(g_xl + (size_t)s * 64 + c0);

        for (int jp = 0; jp < npair; jp++) {
            float4 cur = xl;
            int ecur = 2 * jp + half;
            if (jp + 1 < npair) {
                int sn = __shfl_sync(FULL, my_s, 2 * (jp + 1) + half);
                xl = *(const float4*)(g_xl + (size_t)sn * 64 + c0);
            }
            float p = lrelu(cur.x + xr4.x) * a4.x
                    + lrelu(cur.y + xr4.y) * a4.y
                    + lrelu(cur.z + xr4.z) * a4.z
                    + lrelu(cur.w + xr4.w) * a4.w;
            p += __shfl_xor_sync(FULL, p, 1);
            p += __shfl_xor_sync(FULL, p, 2);
            float ex = __expf(p);
            if (ecur >= n) ex = 0.f;               // odd tail: upper half idle
            denom += ex;
            ac0 += ex * cur.x;
            ac1 += ex * cur.y;
            ac2 += ex * cur.z;
            ac3 += ex * cur.w;
        }
    }

    denom += __shfl_xor_sync(FULL, denom, 16);
    ac0   += __shfl_xor_sync(FULL, ac0, 16);
    ac1   += __shfl_xor_sync(FULL, ac1, 16);
    ac2   += __shfl_xor_sync(FULL, ac2, 16);
    ac3   += __shfl_xor_sync(FULL, ac3, 16);

    if (half == 0) {
        float inv = 1.f / (denom + 1e-16f);
        float4 b4 = *(const float4*)(b + c0);
        float4 v = make_float4(ac0 * inv + b4.x, ac1 * inv + b4.y,
                               ac2 * inv + b4.z, ac3 * inv + b4.w);
        if (layer < 2) {
            v.x = fmaxf(v.x, 0.f); v.y = fmaxf(v.y, 0.f);
            v.z = fmaxf(v.z, 0.f); v.w = fmaxf(v.w, 0.f);
            *(float4*)(g_h + (size_t)d * 64 + c0) = v;
        } else {
            *(float4*)(dout + (size_t)d * 64 + c0) = v;
        }
    }
}

extern "C" void kernel_launch(void* const* d_in, const int* in_sizes, int n_in,
                              void* d_out, int out_size) {
    const float* x = (const float*)d_in[0];
    const int* ei = (const int*)d_in[1];

    cudaFuncSetAttribute(gemm_lr, cudaFuncAttributeMaxDynamicSharedMemorySize,
                         GEMM_SMEM_BYTES);

    // Fork/join resources (host-side objects only; no device memory).
    cudaStream_t s2;
    cudaStreamCreate(&s2);
    cudaEvent_t eFork, eJoin;
    cudaEventCreateWithFlags(&eFork, cudaEventDisableTiming);
    cudaEventCreateWithFlags(&eJoin, cudaEventDisableTiming);

    // main stream: init (feeds both branches)
    init_csr<<<NBLK, 256>>>(ei);
    cudaEventRecord(eFork, 0);

    // branch A (s2): CSR build
    cudaStreamWaitEvent(s2, eFork, 0);
    hist_dst<<<(EE + 255) / 256, 256, 0, s2>>>(ei);
    scan_part<<<NBLK, 256, 0, s2>>>();
    scan_top<<<1, 512, 0, s2>>>();
    scan_apply<<<NBLK, 256, 0, s2>>>();
    scatter_csr<<<(EE + 255) / 256, 256, 0, s2>>>(ei);
    cudaEventRecord(eJoin, s2);

    // branch B (main): layer-0 GEMM, concurrent with CSR build
    gemm_lr<<<(NN + 63) / 64, 256, GEMM_SMEM_BYTES>>>(
        x, 0, (const float*)d_in[2], (const float*)d_in[3]);

    // join: node_agg needs both CSR and gemm0
    cudaStreamWaitEvent(0, eJoin, 0);

    for (int l = 0; l < 3; l++) {
        const float* a = (const float*)d_in[4 + 4 * l];
        const float* b = (const float*)d_in[5 + 4 * l];
        if (l > 0) {
            gemm_lr<<<(NN + 63) / 64, 256, GEMM_SMEM_BYTES>>>(
                x, 1, (const float*)d_in[2 + 4 * l],
                (const float*)d_in[3 + 4 * l]);
        }
        node_agg<<<(NN * 32 + 255) / 256, 256>>>(a, b, (float*)d_out, l);
    }
}

// round 15
// speedup vs baseline: 1.4357x; 1.0079x over previous
#include <cuda_runtime.h>
#include <cstdint>

// GATv2 x3 layers. N=100000 nodes, E=1000000 edges, C=64, H=4, O=16.
//
// Round-15 change: gemm split into column-halves (blockIdx.y: 0 -> Wl/g_xl,
// 1 -> Wr/g_xr). Smem per block 52KB -> 35KB => 6 blocks/SM (48 warps, 75%
// occ) to hide the LDS->split->MMA latency. All else identical to the
// 316.6us kernel (3xTF32 tensor gemm + fused CSR node_agg + stream overlap).

#define NN 100000
#define EE 1000000
#define CC 64
#define HH 4
#define NBLK ((NN + 255) / 256)   // 391
#define FULL 0xffffffffu

// smem strides (floats): conflict-free fragment loads at stride 68
//   W rows: bank = (4t + 8s + g) % 32  -> distinct across a warp
//   X rows: bank = (4g + t) % 32       -> distinct across a warp
#define S_STRIDE 68
#define GEMM_SMEM_BYTES (2 * 64 * S_STRIDE * 4)   // 34816

// ---- scratch (device globals; no runtime allocation allowed) ----
__device__ float g_xl[NN * CC];
__device__ float g_xr[NN * CC];
__device__ float g_h[NN * CC];
__device__ int   g_srcs[EE];       // CSR: src sorted by dst
__device__ int   g_cnt[NN];
__device__ int   g_off[NN + 1];
__device__ int   g_cur[NN];
__device__ int   g_bsum[NBLK + 1];
__device__ int   g_bbase[NBLK + 1];
__device__ int   g_is64;

// leaky-relu(0.2): 0.6v + 0.4|v|
__device__ __forceinline__ float lrelu(float v) {
    return fmaf(0.4f, fabsf(v), 0.6f * v);
}

// Dekker-style tf32 split: hi = top mantissa bits (exact fp32), lo = v - hi.
__device__ __forceinline__ void tf32_split(float v, uint32_t& hi, uint32_t& lo) {
    uint32_t h = __float_as_uint(v) & 0xFFFFE000u;
    hi = h;
    lo = __float_as_uint(v - __uint_as_float(h));
}

__device__ __forceinline__ void mma_tf32(float* d, const uint32_t* a,
                                         uint32_t b0, uint32_t b1) {
    asm volatile(
        "mma.sync.aligned.m16n8k8.row.col.f32.tf32.tf32.f32 "
        "{%0,%1,%2,%3}, {%4,%5,%6,%7}, {%8,%9}, {%0,%1,%2,%3};"
        : "+f"(d[0]), "+f"(d[1]), "+f"(d[2]), "+f"(d[3])
        : "r"(a[0]), "r"(a[1]), "r"(a[2]), "r"(a[3]), "r"(b0), "r"(b1));
}

// ---- detect int32 vs int64 edge_index + zero counts (one kernel) ----
__global__ void init_csr(const int* __restrict__ w) {
    int t = blockIdx.x * blockDim.x + threadIdx.x;
    if (t < NN) g_cnt[t] = 0;
    if (t == 0) {
        int allz = 1;
#pragma unroll
        for (int i = 0; i < 128; i++) {
            if (w[2 * i + 1] != 0) { allz = 0; break; }
        }
        g_is64 = allz;
    }
}

// ---- dst histogram straight off edge_index ----
__global__ void hist_dst(const int* __restrict__ w) {
    int t = blockIdx.x * blockDim.x + threadIdx.x;
    if (t >= EE) return;
    int d = g_is64 ? w[2 * (EE + t)] : w[EE + t];
    d = min(max(d, 0), NN - 1);
    atomicAdd(&g_cnt[d], 1);
}

// ---- 3-kernel exclusive scan of g_cnt -> g_off / g_cur ----
__global__ void scan_part() {
    __shared__ int sh[256];
    int t = threadIdx.x;
    int i = blockIdx.x * 256 + t;
    int v = (i < NN) ? g_cnt[i] : 0;
    sh[t] = v;
    __syncthreads();
    for (int d = 128; d > 0; d >>= 1) {
        if (t < d) sh[t] += sh[t + d];
        __syncthreads();
    }
    if (t == 0) g_bsum[blockIdx.x] = sh[0];
}

__global__ void scan_top() {   // 1 block, 512 threads (NBLK=391)
    __shared__ int sh[512];
    int t = threadIdx.x;
    int v = (t < NBLK) ? g_bsum[t] : 0;
    sh[t] = v;
    __syncthreads();
    for (int d = 1; d < 512; d <<= 1) {
        int tmp = (t >= d) ? sh[t - d] : 0;
        __syncthreads();
        sh[t] += tmp;
        __syncthreads();
    }
    if (t < NBLK) g_bbase[t] = sh[t] - v;   // exclusive
}

__global__ void scan_apply() {
    __shared__ int sh[256];
    int t = threadIdx.x;
    int i = blockIdx.x * 256 + t;
    int v = (i < NN) ? g_cnt[i] : 0;
    sh[t] = v;
    __syncthreads();
    for (int d = 1; d < 256; d <<= 1) {
        int tmp = (t >= d) ? sh[t - d] : 0;
        __syncthreads();
        sh[t] += tmp;
        __syncthreads();
    }
    int excl = sh[t] - v + g_bbase[blockIdx.x];
    if (i < NN) {
        g_off[i] = excl;
        g_cur[i] = excl;
    }
    if (i == 0) g_off[NN] = EE;
}

__global__ void scatter_csr(const int* __restrict__ w) {
    int t = blockIdx.x * blockDim.x + threadIdx.x;
    if (t >= EE) return;
    int s, d;
    if (g_is64) {
        s = w[2 * t];
        d = w[2 * (EE + t)];
    } else {
        s = w[t];
        d = w[EE + t];
    }
    s = min(max(s, 0), NN - 1);
    d = min(max(d, 0), NN - 1);
    int pos = atomicAdd(&g_cur[d], 1);
    g_srcs[pos] = s;
}

// ---- xl/xr = in @ Wl/Wr on tensor cores (3xTF32), column-half blocks ----
// grid (ceil(N/64), 2): blockIdx.y 0 -> Wl->g_xl, 1 -> Wr->g_xr.
// 8 warps: warp w -> m-tile (w&3)*16, n cols (w>>2)*32 .. +31 (4 n8 tiles).
__global__ void __launch_bounds__(256) gemm_lr(
        const float* __restrict__ xin, int use_gh,
        const float* __restrict__ Wl, const float* __restrict__ Wr) {
    extern __shared__ float smf[];
    float* sW = smf;                       // [64][S_STRIDE], 64 cols
    float* sx = smf + 64 * S_STRIDE;       // [64][S_STRIDE]
    const float* in = use_gh ? g_h : xin;
    const float* W = blockIdx.y ? Wr : Wl;
    float* out = blockIdx.y ? g_xr : g_xl;

    int tid = threadIdx.x;

    for (int i = tid; i < 4096; i += 256) {
        int k = i >> 6, c = i & 63;
        sW[k * S_STRIDE + c] = W[i];
    }
    int base = blockIdx.x * 64;
    for (int i = tid; i < 1024; i += 256) {        // 64 nodes x 16 float4
        int n = i >> 4, q = i & 15;
        int node = base + n;
        float4 v = make_float4(0.f, 0.f, 0.f, 0.f);
        if (node < NN) v = ((const float4*)(in + (size_t)node * 64))[q];
        *(float4*)&sx[n * S_STRIDE + 4 * q] = v;
    }
    __syncthreads();

    int w = tid >> 5, lane = tid & 31;
    int g = lane >> 2, t = lane & 3;
    int m0 = (w & 3) << 4;
    int nb = (w >> 2) << 5;                // 0 or 32

    float acc[4][4];
#pragma unroll
    for (int s = 0; s < 4; s++) {
        acc[s][0] = 0.f; acc[s][1] = 0.f; acc[s][2] = 0.f; acc[s][3] = 0.f;
    }

#pragma unroll
    for (int ks = 0; ks < 8; ks++) {
        int k0 = ks * 8;
        int ra = (m0 + g) * S_STRIDE + k0 + t;
        int rb = (m0 + g + 8) * S_STRIDE + k0 + t;
        uint32_t ah[4], al[4];
        tf32_split(sx[ra],     ah[0], al[0]);
        tf32_split(sx[rb],     ah[1], al[1]);
        tf32_split(sx[ra + 4], ah[2], al[2]);
        tf32_split(sx[rb + 4], ah[3], al[3]);
#pragma unroll
        for (int s = 0; s < 4; s++) {
            int col = nb + s * 8 + g;
            uint32_t bh0, bl0, bh1, bl1;
            tf32_split(sW[(k0 + t) * S_STRIDE + col],     bh0, bl0);
            tf32_split(sW[(k0 + t + 4) * S_STRIDE + col], bh1, bl1);
            mma_tf32(acc[s], ah, bh0, bh1);   // hi*hi
            mma_tf32(acc[s], ah, bl0, bl1);   // hi*lo
            mma_tf32(acc[s], al, bh0, bh1);   // lo*hi
        }
    }

    int node0 = base + m0 + g;
    int node1 = node0 + 8;
#pragma unroll
    for (int s = 0; s < 4; s++) {
        int col = nb + s * 8 + 2 * t;
        if (node0 < NN)
            *(float2*)(out + (size_t)node0 * 64 + col) =
                make_float2(acc[s][0], acc[s][1]);
        if (node1 < NN)
            *(float2*)(out + (size_t)node1 * 64 + col) =
                make_float2(acc[s][2], acc[s][3]);
    }
}

// ---- fused edge phase: one warp per dst node, 2 edges per iteration ----
__global__ void node_agg(const float* __restrict__ a, const float* __restrict__ b,
                         float* __restrict__ dout, int layer) {
    int gw = (blockIdx.x * blockDim.x + threadIdx.x) >> 5;
    int lane = threadIdx.x & 31;
    if (gw >= NN) return;
    int d = gw;
    int half = lane >> 4;
    int q = lane & 15;
    int c0 = q * 4;

    float4 xr4 = *(const float4*)(g_xr + (size_t)d * 64 + c0);
    float4 a4  = *(const float4*)(a + c0);

    int beg = g_off[d], end = g_off[d + 1];
    float denom = 0.f;
    float ac0 = 0.f, ac1 = 0.f, ac2 = 0.f, ac3 = 0.f;

    for (int base = beg; base < end; base += 32) {
        int n = min(32, end - base);
        int my_s = (base + lane < end) ? g_srcs[base + lane] : 0;
        int npair = (n + 1) >> 1;

        int s = __shfl_sync(FULL, my_s, half);     // edge {0,1}
        float4 xl = *(const float4*)(g_xl + (size_t)s * 64 + c0);

        for (int jp = 0; jp < npair; jp++) {
            float4 cur = xl;
            int ecur = 2 * jp + half;
            if (jp + 1 < npair) {
                int sn = __shfl_sync(FULL, my_s, 2 * (jp + 1) + half);
                xl = *(const float4*)(g_xl + (size_t)sn * 64 + c0);
            }
            float p = lrelu(cur.x + xr4.x) * a4.x
                    + lrelu(cur.y + xr4.y) * a4.y
                    + lrelu(cur.z + xr4.z) * a4.z
                    + lrelu(cur.w + xr4.w) * a4.w;
            p += __shfl_xor_sync(FULL, p, 1);
            p += __shfl_xor_sync(FULL, p, 2);
            float ex = __expf(p);
            if (ecur >= n) ex = 0.f;               // odd tail: upper half idle
            denom += ex;
            ac0 += ex * cur.x;
            ac1 += ex * cur.y;
            ac2 += ex * cur.z;
            ac3 += ex * cur.w;
        }
    }

    denom += __shfl_xor_sync(FULL, denom, 16);
    ac0   += __shfl_xor_sync(FULL, ac0, 16);
    ac1   += __shfl_xor_sync(FULL, ac1, 16);
    ac2   += __shfl_xor_sync(FULL, ac2, 16);
    ac3   += __shfl_xor_sync(FULL, ac3, 16);

    if (half == 0) {
        float inv = 1.f / (denom + 1e-16f);
        float4 b4 = *(const float4*)(b + c0);
        float4 v = make_float4(ac0 * inv + b4.x, ac1 * inv + b4.y,
                               ac2 * inv + b4.z, ac3 * inv + b4.w);
        if (layer < 2) {
            v.x = fmaxf(v.x, 0.f); v.y = fmaxf(v.y, 0.f);
            v.z = fmaxf(v.z, 0.f); v.w = fmaxf(v.w, 0.f);
            *(float4*)(g_h + (size_t)d * 64 + c0) = v;
        } else {
            *(float4*)(dout + (size_t)d * 64 + c0) = v;
        }
    }
}

extern "C" void kernel_launch(void* const* d_in, const int* in_sizes, int n_in,
                              void* d_out, int out_size) {
    const float* x = (const float*)d_in[0];
    const int* ei = (const int*)d_in[1];

    cudaFuncSetAttribute(gemm_lr, cudaFuncAttributeMaxDynamicSharedMemorySize,
                         GEMM_SMEM_BYTES);

    // Fork/join resources (host-side objects only; no device memory).
    cudaStream_t s2;
    cudaStreamCreate(&s2);
    cudaEvent_t eFork, eJoin;
    cudaEventCreateWithFlags(&eFork, cudaEventDisableTiming);
    cudaEventCreateWithFlags(&eJoin, cudaEventDisableTiming);

    dim3 ggrid((NN + 63) / 64, 2);

    // main stream: init (feeds both branches)
    init_csr<<<NBLK, 256>>>(ei);
    cudaEventRecord(eFork, 0);

    // branch A (s2): CSR build
    cudaStreamWaitEvent(s2, eFork, 0);
    hist_dst<<<(EE + 255) / 256, 256, 0, s2>>>(ei);
    scan_part<<<NBLK, 256, 0, s2>>>();
    scan_top<<<1, 512, 0, s2>>>();
    scan_apply<<<NBLK, 256, 0, s2>>>();
    scatter_csr<<<(EE + 255) / 256, 256, 0, s2>>>(ei);
    cudaEventRecord(eJoin, s2);

    // branch B (main): layer-0 GEMM, concurrent with CSR build
    gemm_lr<<<ggrid, 256, GEMM_SMEM_BYTES>>>(
        x, 0, (const float*)d_in[2], (const float*)d_in[3]);

    // join: node_agg needs both CSR and gemm0
    cudaStreamWaitEvent(0, eJoin, 0);

    for (int l = 0; l < 3; l++) {
        const float* a = (const float*)d_in[4 + 4 * l];
        const float* b = (const float*)d_in[5 + 4 * l];
        if (l > 0) {
            gemm_lr<<<ggrid, 256, GEMM_SMEM_BYTES>>>(
                x, 1, (const float*)d_in[2 + 4 * l],
                (const float*)d_in[3 + 4 * l]);
        }
        node_agg<<<(NN * 32 + 255) / 256, 256>>>(a, b, (float*)d_out, l);
    }
}